// round 1
// baseline (speedup 1.0000x reference)
#include <cuda_runtime.h>
#include <math.h>

// Problem constants
#define BATCH 16
#define CH    512
#define NSP   1024          // H*W
#define HEADS 4
#define HD    128
#define GROUPS_N 32
#define GSIZE (16*1024)     // (CH/GROUPS_N)*NSP
#define EPSV  1e-5f
#define ATT_SCALE 0.08838834764831845f  // 1/sqrt(128)

// Scratch (device globals; no cudaMalloc allowed)
__device__ float g_h[(size_t)BATCH*CH*NSP];        // normalized input, 32 MB
__device__ float g_qkv[(size_t)BATCH*3*CH*NSP];    // qkv, 96 MB
__device__ float g_o[(size_t)BATCH*CH*NSP];        // attention output, 32 MB

// ---------------------------------------------------------------------------
// GroupNorm: one block per (b, group). Group data is contiguous (16 channels
// x 1024 spatial = 16384 floats).
// ---------------------------------------------------------------------------
__global__ __launch_bounds__(256) void gn_kernel(
    const float* __restrict__ x,
    const float* __restrict__ nw,
    const float* __restrict__ nb)
{
    int bg = blockIdx.x;                    // 0..511
    int g  = bg % GROUPS_N;
    const float* xp = x   + (size_t)bg * GSIZE;
    float*       hp = g_h + (size_t)bg * GSIZE;

    float s = 0.f, s2 = 0.f;
    for (int i = threadIdx.x; i < GSIZE; i += 256) {
        float v = xp[i];
        s += v; s2 += v * v;
    }
    __shared__ float rs[256], rs2[256];
    rs[threadIdx.x] = s; rs2[threadIdx.x] = s2;
    __syncthreads();
    for (int o = 128; o > 0; o >>= 1) {
        if (threadIdx.x < o) {
            rs[threadIdx.x]  += rs[threadIdx.x + o];
            rs2[threadIdx.x] += rs2[threadIdx.x + o];
        }
        __syncthreads();
    }
    float mu   = rs[0] * (1.f / GSIZE);
    float var  = rs2[0] * (1.f / GSIZE) - mu * mu;
    float rinv = rsqrtf(var + EPSV);

    for (int i = threadIdx.x; i < GSIZE; i += 256) {
        int c = g * 16 + (i >> 10);
        hp[i] = (xp[i] - mu) * rinv * nw[c] + nb[c];
    }
}

// ---------------------------------------------------------------------------
// Batched GEMM: out[b][o][n] = bias[o] + sum_c w[o][c] * in[b][c][n]
//               (+ resid[b][o][n] if resid != nullptr)
// Tiles: 64(o) x 64(n), K-tile 16. 256 threads, 4x4 microtile.
// grid = (NSP/64, OC/64, BATCH)
// ---------------------------------------------------------------------------
__global__ __launch_bounds__(256) void gemm_kernel(
    float* __restrict__ out,
    const float* __restrict__ w,
    const float* __restrict__ bias,
    const float* __restrict__ in,
    const float* __restrict__ resid,
    int OC)
{
    __shared__ float ws[16 * 68];   // [kk][oi], padded row=68 (16B aligned, low conflict)
    __shared__ float is[16 * 64];   // [kk][nj]

    int n0 = blockIdx.x * 64;
    int o0 = blockIdx.y * 64;
    int b  = blockIdx.z;
    int tid = threadIdx.x;
    int tx = tid & 15, ty = tid >> 4;

    const float* inb = in + (size_t)b * CH * NSP;

    float acc[4][4];
#pragma unroll
    for (int i = 0; i < 4; i++)
#pragma unroll
        for (int j = 0; j < 4; j++) acc[i][j] = 0.f;

    for (int c0 = 0; c0 < CH; c0 += 16) {
        __syncthreads();
#pragma unroll
        for (int t = 0; t < 4; t++) {
            int e  = t * 256 + tid;
            int oi = e >> 4, kk = e & 15;
            ws[kk * 68 + oi] = w[(size_t)(o0 + oi) * CH + c0 + kk];
            int kk2 = e >> 6, j = e & 63;
            is[kk2 * 64 + j] = inb[(size_t)(c0 + kk2) * NSP + n0 + j];
        }
        __syncthreads();
#pragma unroll
        for (int kk = 0; kk < 16; kk++) {
            float4 a  = *(const float4*)&ws[kk * 68 + 4 * ty];
            float4 bb = *(const float4*)&is[kk * 64 + 4 * tx];
            acc[0][0] += a.x * bb.x; acc[0][1] += a.x * bb.y;
            acc[0][2] += a.x * bb.z; acc[0][3] += a.x * bb.w;
            acc[1][0] += a.y * bb.x; acc[1][1] += a.y * bb.y;
            acc[1][2] += a.y * bb.z; acc[1][3] += a.y * bb.w;
            acc[2][0] += a.z * bb.x; acc[2][1] += a.z * bb.y;
            acc[2][2] += a.z * bb.z; acc[2][3] += a.z * bb.w;
            acc[3][0] += a.w * bb.x; acc[3][1] += a.w * bb.y;
            acc[3][2] += a.w * bb.z; acc[3][3] += a.w * bb.w;
        }
    }

#pragma unroll
    for (int i = 0; i < 4; i++) {
        int o = o0 + 4 * ty + i;
        float bi = bias[o];
        size_t off = ((size_t)b * OC + o) * NSP + n0 + 4 * tx;
        float4 v;
        v.x = acc[i][0] + bi; v.y = acc[i][1] + bi;
        v.z = acc[i][2] + bi; v.w = acc[i][3] + bi;
        if (resid) {
            float4 r = *(const float4*)&resid[off];
            v.x += r.x; v.y += r.y; v.z += r.z; v.w += r.w;
        }
        *(float4*)&out[off] = v;
    }
}

// ---------------------------------------------------------------------------
// Flash attention (fp32, non-causal). One block = 64 queries of one (b,h).
// Streams 64-key tiles; online softmax; output normalized at the end.
// grid = (NSP/64, BATCH*HEADS), 256 threads.
// Dynamic smem layout:
//   qs[128][64]   (32 KB)  — Q tile, [d][q]
//   ks[128][64]   (32 KB)  — K tile, [d][k]
//   vs[128][65]   (32.5KB) — V tile, [d][k] padded (also reused for output staging)
//   ps[64][65]    (16.3KB) — probabilities, [q][k] padded
// ---------------------------------------------------------------------------
__global__ __launch_bounds__(256) void flash_kernel()
{
    extern __shared__ float sm[];
    float* qs = sm;            // 8192
    float* ks = qs + 8192;     // 8192
    float* vs = ks + 8192;     // 8320
    float* ps = vs + 8320;     // 4160

    int n0 = blockIdx.x * 64;
    int bh = blockIdx.y;
    int b = bh >> 2, h = bh & 3;
    const float* qp = g_qkv + ((size_t)b * 3 * CH + 0 * CH + h * HD) * NSP;
    const float* kp = g_qkv + ((size_t)b * 3 * CH + 1 * CH + h * HD) * NSP;
    const float* vp = g_qkv + ((size_t)b * 3 * CH + 2 * CH + h * HD) * NSP;

    int tid = threadIdx.x;
    int tx = tid & 15, ty = tid >> 4;

    // Load Q tile [128 dims][64 queries]
#pragma unroll 8
    for (int t = 0; t < 32; t++) {
        int e = t * 256 + tid;
        int d = e >> 6, qi = e & 63;
        qs[d * 64 + qi] = qp[(size_t)d * NSP + n0 + qi];
    }

    float acc[4][8];   // [query i][dim group j]; query = 4*ty+i, dim = 16*j+tx
#pragma unroll
    for (int i = 0; i < 4; i++)
#pragma unroll
        for (int j = 0; j < 8; j++) acc[i][j] = 0.f;
    float rm[4], rl[4];
#pragma unroll
    for (int i = 0; i < 4; i++) { rm[i] = -1e30f; rl[i] = 0.f; }

    for (int k0 = 0; k0 < NSP; k0 += 64) {
        __syncthreads();  // protect ks/vs/ps from previous iteration's readers
#pragma unroll 8
        for (int t = 0; t < 32; t++) {
            int e = t * 256 + tid;
            int d = e >> 6, kk = e & 63;
            ks[d * 64 + kk] = kp[(size_t)d * NSP + k0 + kk];
            vs[d * 65 + kk] = vp[(size_t)d * NSP + k0 + kk];
        }
        __syncthreads();

        // S = Q^T K  (4x4 microtile per thread)
        float s[4][4];
#pragma unroll
        for (int i = 0; i < 4; i++)
#pragma unroll
            for (int j = 0; j < 4; j++) s[i][j] = 0.f;

#pragma unroll 4
        for (int d = 0; d < HD; d++) {
            float4 a  = *(const float4*)&qs[d * 64 + 4 * ty];
            float4 bb = *(const float4*)&ks[d * 64 + 4 * tx];
            s[0][0] += a.x * bb.x; s[0][1] += a.x * bb.y;
            s[0][2] += a.x * bb.z; s[0][3] += a.x * bb.w;
            s[1][0] += a.y * bb.x; s[1][1] += a.y * bb.y;
            s[1][2] += a.y * bb.z; s[1][3] += a.y * bb.w;
            s[2][0] += a.z * bb.x; s[2][1] += a.z * bb.y;
            s[2][2] += a.z * bb.z; s[2][3] += a.z * bb.w;
            s[3][0] += a.w * bb.x; s[3][1] += a.w * bb.y;
            s[3][2] += a.w * bb.z; s[3][3] += a.w * bb.w;
        }

        // Online softmax per query row (reduce across tx lanes; xor 1,2,4,8
        // stays within the 16-lane tx group since ty is lane bit 4).
#pragma unroll
        for (int i = 0; i < 4; i++) {
            float mx = -1e30f;
#pragma unroll
            for (int j = 0; j < 4; j++) {
                s[i][j] *= ATT_SCALE;
                mx = fmaxf(mx, s[i][j]);
            }
#pragma unroll
            for (int o = 1; o < 16; o <<= 1)
                mx = fmaxf(mx, __shfl_xor_sync(0xffffffffu, mx, o));
            float mnew  = fmaxf(rm[i], mx);
            float alpha = expf(rm[i] - mnew);
            float rsum = 0.f;
#pragma unroll
            for (int j = 0; j < 4; j++) {
                float p = expf(s[i][j] - mnew);
                s[i][j] = p;
                rsum += p;
            }
#pragma unroll
            for (int o = 1; o < 16; o <<= 1)
                rsum += __shfl_xor_sync(0xffffffffu, rsum, o);
            rl[i] = rl[i] * alpha + rsum;
            rm[i] = mnew;
#pragma unroll
            for (int j = 0; j < 8; j++) acc[i][j] *= alpha;
#pragma unroll
            for (int j = 0; j < 4; j++)
                ps[(4 * ty + i) * 65 + 4 * tx + j] = s[i][j];
        }
        __syncthreads();

        // O += P V^T : acc[i][j] += sum_k ps[q][k] * vs[16j+tx][k]
#pragma unroll 2
        for (int k = 0; k < 64; k++) {
            float p0 = ps[(4 * ty + 0) * 65 + k];
            float p1 = ps[(4 * ty + 1) * 65 + k];
            float p2 = ps[(4 * ty + 2) * 65 + k];
            float p3 = ps[(4 * ty + 3) * 65 + k];
#pragma unroll
            for (int j = 0; j < 8; j++) {
                float v = vs[(16 * j + tx) * 65 + k];
                acc[0][j] += p0 * v;
                acc[1][j] += p1 * v;
                acc[2][j] += p2 * v;
                acc[3][j] += p3 * v;
            }
        }
    }

    __syncthreads();
    // Normalize and stage through smem (reuse vs as os[128][65]) for
    // coalesced global stores.
    float* os = vs;
#pragma unroll
    for (int i = 0; i < 4; i++) {
        float inv = 1.f / rl[i];
#pragma unroll
        for (int j = 0; j < 8; j++)
            os[(16 * j + tx) * 65 + 4 * ty + i] = acc[i][j] * inv;
    }
    __syncthreads();

    float* op = g_o + ((size_t)b * CH + h * HD) * NSP;
#pragma unroll 8
    for (int t = 0; t < 32; t++) {
        int e = t * 256 + tid;
        int d = e >> 6, q = e & 63;
        op[(size_t)d * NSP + n0 + q] = os[d * 65 + q];
    }
}

// ---------------------------------------------------------------------------
// Launch
// ---------------------------------------------------------------------------
extern "C" void kernel_launch(void* const* d_in, const int* in_sizes, int n_in,
                              void* d_out, int out_size)
{
    const float* x      = (const float*)d_in[0];
    const float* norm_w = (const float*)d_in[1];
    const float* norm_b = (const float*)d_in[2];
    const float* qkv_w  = (const float*)d_in[3];
    const float* qkv_b  = (const float*)d_in[4];
    const float* proj_w = (const float*)d_in[5];
    const float* proj_b = (const float*)d_in[6];
    float* out = (float*)d_out;

    float* hptr;   cudaGetSymbolAddress((void**)&hptr,   g_h);
    float* qkvptr; cudaGetSymbolAddress((void**)&qkvptr, g_qkv);
    float* optr;   cudaGetSymbolAddress((void**)&optr,   g_o);

    // 1. GroupNorm
    gn_kernel<<<BATCH * GROUPS_N, 256>>>(x, norm_w, norm_b);

    // 2. QKV projection: [1536 x 512] x [512 x 1024] per batch
    {
        dim3 grid(NSP / 64, (3 * CH) / 64, BATCH);
        gemm_kernel<<<grid, 256>>>(qkvptr, qkv_w, qkv_b, hptr, nullptr, 3 * CH);
    }

    // 3. Flash attention
    {
        int smem = (8192 + 8192 + 8320 + 4160) * (int)sizeof(float);  // 115456 B
        cudaFuncSetAttribute(flash_kernel,
                             cudaFuncAttributeMaxDynamicSharedMemorySize, smem);
        dim3 grid(NSP / 64, BATCH * HEADS);
        flash_kernel<<<grid, 256, smem>>>();
    }

    // 4. Output projection + residual
    {
        dim3 grid(NSP / 64, CH / 64, BATCH);
        gemm_kernel<<<grid, 256>>>(out, proj_w, proj_b, optr, x, CH);
    }
}

// round 3
// speedup vs baseline: 3.0892x; 3.0892x over previous
#include <cuda_runtime.h>
#include <cstdint>
#include <math.h>

#define BATCH 16
#define CH    512
#define NSP   1024
#define HEADS 4
#define HD    128
#define GROUPS_N 32
#define GSIZE (16*1024)
#define EPSV  1e-5f
#define ATT_SCALE 0.08838834764831845f

// ---------------------------------------------------------------------------
// Scratch (device globals; no cudaMalloc allowed). All GEMM operands stored
// pre-rounded to tf32 (fp32 bit pattern, mantissa rounded) so the MMA's
// internal truncation is exact (no bias).
// ---------------------------------------------------------------------------
__device__ float g_ht  [(size_t)BATCH*NSP*CH];        // GN out   [b][n][c]
__device__ float g_qkvt[(size_t)BATCH*NSP*(3*CH)];    // QKV out  [b][n][o] (Q,K used; V cols unused)
__device__ float g_vt  [(size_t)BATCH*HEADS*HD*NSP];  // V        [b,h][d][m]
__device__ float g_s   [(size_t)BATCH*HEADS*NSP*NSP]; // scores/probs [bh][q][k]
__device__ float g_ot  [(size_t)BATCH*NSP*CH];        // attn out [b][n][c]
__device__ float g_wq  [(size_t)(3*CH)*CH];           // tf32-rounded qkv_w
__device__ float g_wp  [(size_t)CH*CH];               // tf32-rounded proj_w

// ---------------------------------------------------------------------------
// Helpers
// ---------------------------------------------------------------------------
__device__ __forceinline__ uint32_t smem_u32(const void* p){
    uint32_t a;
    asm("{ .reg .u64 t; cvta.to.shared.u64 t, %1; cvt.u32.u64 %0, t; }" : "=r"(a) : "l"(p));
    return a;
}
__device__ __forceinline__ uint32_t cvt_tf32(float f){
    uint32_t o; asm("cvt.rna.tf32.f32 %0, %1;" : "=r"(o) : "f"(f)); return o;
}
__device__ __forceinline__ float rnd_tf32(float f){ return __uint_as_float(cvt_tf32(f)); }

__device__ __forceinline__ void cp16(uint32_t dst, const float* src){
    asm volatile("cp.async.cg.shared.global [%0], [%1], 16;" :: "r"(dst), "l"(src) : "memory");
}
#define CP_COMMIT() asm volatile("cp.async.commit_group;" ::: "memory")
#define CP_WAIT2()  asm volatile("cp.async.wait_group 2;" ::: "memory")
#define CP_WAIT0()  asm volatile("cp.async.wait_group 0;" ::: "memory")

#define MMA8(c, a, b) \
    asm volatile("mma.sync.aligned.m16n8k8.row.col.f32.tf32.tf32.f32 " \
        "{%0,%1,%2,%3},{%4,%5,%6,%7},{%8,%9},{%0,%1,%2,%3};" \
        : "+f"((c)[0]), "+f"((c)[1]), "+f"((c)[2]), "+f"((c)[3]) \
        : "r"((a)[0]), "r"((a)[1]), "r"((a)[2]), "r"((a)[3]), \
          "r"((b)[0]), "r"((b)[1]))

// ---------------------------------------------------------------------------
// Weight pre-round: qkv_w / proj_w -> tf32-rounded device copies
// ---------------------------------------------------------------------------
__global__ __launch_bounds__(256) void cvtw_kernel(
    const float* __restrict__ qw, const float* __restrict__ pw)
{
    int i = blockIdx.x * 256 + threadIdx.x;
    if (i < 3*CH*CH) g_wq[i] = rnd_tf32(qw[i]);
    if (i < CH*CH)   g_wp[i] = rnd_tf32(pw[i]);
}

// ---------------------------------------------------------------------------
// GroupNorm + transpose -> g_ht[b][n][c], tf32-rounded
// ---------------------------------------------------------------------------
__global__ __launch_bounds__(256) void gn_kernel(
    const float* __restrict__ x,
    const float* __restrict__ nw,
    const float* __restrict__ nb)
{
    __shared__ float t[16][257];
    int bg = blockIdx.x;
    int b = bg >> 5, g = bg & 31;
    const float* xp = x + (size_t)bg * GSIZE;
    int tid = threadIdx.x;

    float s = 0.f, s2 = 0.f;
    for (int i = tid; i < GSIZE; i += 256) { float v = xp[i]; s += v; s2 += v * v; }
    float* rs  = &t[0][0];
    float* rs2 = rs + 1024;
    rs[tid] = s; rs2[tid] = s2;
    __syncthreads();
    for (int o = 128; o > 0; o >>= 1) {
        if (tid < o) { rs[tid] += rs[tid + o]; rs2[tid] += rs2[tid + o]; }
        __syncthreads();
    }
    float mu   = rs[0] * (1.f / GSIZE);
    float var  = rs2[0] * (1.f / GSIZE) - mu * mu;
    float rinv = rsqrtf(var + EPSV);
    __syncthreads();

    int cl = tid & 15;
    float wc = nw[g * 16 + cl] * rinv;
    float bc = nb[g * 16 + cl] - mu * wc;
    float* hp = g_ht + (size_t)b * NSP * CH + g * 16;

    for (int n0 = 0; n0 < NSP; n0 += 256) {
#pragma unroll
        for (int c = 0; c < 16; c++) t[c][tid] = xp[c * NSP + n0 + tid];
        __syncthreads();
#pragma unroll
        for (int j = 0; j < 16; j++) {
            int nn = (tid >> 4) + j * 16;
            hp[(size_t)(n0 + nn) * CH + cl] = rnd_tf32(t[cl][nn] * wc + bc);
        }
        __syncthreads();
    }
}

// ---------------------------------------------------------------------------
// Softmax in-place over g_s rows; output probs tf32-rounded.
// ---------------------------------------------------------------------------
__global__ __launch_bounds__(256) void softmax_kernel()
{
    size_t row = (size_t)blockIdx.x * 8 + (threadIdx.x >> 5);
    int l = threadIdx.x & 31;
    float4* sp = (float4*)(g_s + row * NSP);

    float4 v[8];
    float m = -1e30f;
#pragma unroll
    for (int t = 0; t < 8; t++) {
        v[t] = sp[t * 32 + l];
        v[t].x *= ATT_SCALE; v[t].y *= ATT_SCALE; v[t].z *= ATT_SCALE; v[t].w *= ATT_SCALE;
        m = fmaxf(m, fmaxf(fmaxf(v[t].x, v[t].y), fmaxf(v[t].z, v[t].w)));
    }
#pragma unroll
    for (int o = 16; o > 0; o >>= 1) m = fmaxf(m, __shfl_xor_sync(0xffffffffu, m, o));
    float s = 0.f;
#pragma unroll
    for (int t = 0; t < 8; t++) {
        v[t].x = __expf(v[t].x - m); v[t].y = __expf(v[t].y - m);
        v[t].z = __expf(v[t].z - m); v[t].w = __expf(v[t].w - m);
        s += v[t].x + v[t].y + v[t].z + v[t].w;
    }
#pragma unroll
    for (int o = 16; o > 0; o >>= 1) s += __shfl_xor_sync(0xffffffffu, s, o);
    float inv = 1.f / s;
#pragma unroll
    for (int t = 0; t < 8; t++) {
        v[t].x = rnd_tf32(v[t].x * inv); v[t].y = rnd_tf32(v[t].y * inv);
        v[t].z = rnd_tf32(v[t].z * inv); v[t].w = rnd_tf32(v[t].w * inv);
        sp[t * 32 + l] = v[t];
    }
}

// ---------------------------------------------------------------------------
// tf32 mma.sync GEMM: D[128m x 128n] = A[m][K] * B[n][K]^T (both K-major)
// 256 threads = 8 warps (2 x 4); warp tile 64x32; m16n8k8 tf32 MMA.
// 3-stage cp.async pipeline, K-chunk 32, smem stride 36 (conflict-free frags).
// MODE 0: QKV   A=g_ht[b],   B=g_wq,  epi: +bias; Q/K->g_qkvt (tf32), V->g_vt trans (tf32)
// MODE 1: S     A=Q slice,   B=K slice,  epi: raw -> g_s
// MODE 2: PV    A=g_s probs, B=g_vt,     epi: tf32 -> g_ot
// MODE 3: proj  A=g_ot[b],   B=g_wp,  epi: +bias +resid trans -> out (fp32)
// ---------------------------------------------------------------------------
#define BK 32
#define ASTR 36
#define TILE_F (128*ASTR)        // 4608 floats per operand tile
#define STAGE_F (2*TILE_F)       // 9216
#define STAGES 3
#define GEMM_SMEM (STAGES*STAGE_F*4)   // 110592 bytes

template<int MODE>
__global__ __launch_bounds__(256) void gemm_tc(
    const float* __restrict__ Wq, const float* __restrict__ Wp,
    const float* __restrict__ bias,
    const float* __restrict__ resid, float* __restrict__ outp)
{
    extern __shared__ float sm[];
    const int tid = threadIdx.x;
    uint32_t smb = smem_u32(sm);

    int m0 = blockIdx.x * 128;
    int n0 = blockIdx.y * 128;
    int z  = blockIdx.z;

    const float *A, *B;
    int lda, ldb, K;
    if (MODE == 0) {
        A = g_ht + ((size_t)z * NSP + m0) * CH; lda = CH;
        B = Wq + (size_t)n0 * CH;               ldb = CH;  K = CH;
    } else if (MODE == 1) {
        int b = z >> 2, h = z & 3;
        const float* base = g_qkvt + (size_t)b * NSP * 1536;
        A = base + (size_t)m0 * 1536 + h * HD;
        B = base + (size_t)n0 * 1536 + 512 + h * HD;
        lda = 1536; ldb = 1536; K = HD;
    } else if (MODE == 2) {
        A = g_s  + (size_t)z * NSP * NSP + (size_t)m0 * NSP; lda = NSP; K = NSP;
        B = g_vt + (size_t)z * HD * NSP;                     ldb = NSP;
    } else {
        A = g_ot + ((size_t)z * NSP + m0) * CH; lda = CH;
        B = Wp + (size_t)n0 * CH;               ldb = CH;  K = CH;
    }

    const int lane = tid & 31, wid = tid >> 5;
    const int wm = wid & 1, wn = wid >> 1;
    const int r_ = tid >> 3;   // 0..31
    const int f_ = tid & 7;    // 0..7

    float acc[4][4][4];
#pragma unroll
    for (int i = 0; i < 4; i++)
#pragma unroll
        for (int j = 0; j < 4; j++)
#pragma unroll
            for (int q = 0; q < 4; q++) acc[i][j][q] = 0.f;

    const int nch = K / BK;

    // async-copy one K-chunk into stage buffer
    auto issue = [&](int ci) {
        int s = ci % STAGES;
        uint32_t as = smb + (uint32_t)(s * STAGE_F) * 4u;
        uint32_t bs = as + (uint32_t)TILE_F * 4u;
        int k0 = ci * BK;
#pragma unroll
        for (int t = 0; t < 4; t++) {
            int r = t * 32 + r_;
            cp16(as + (uint32_t)(r * ASTR + f_ * 4) * 4u, A + (size_t)r * lda + k0 + f_ * 4);
            cp16(bs + (uint32_t)(r * ASTR + f_ * 4) * 4u, B + (size_t)r * ldb + k0 + f_ * 4);
        }
    };

    issue(0); CP_COMMIT();
    if (nch > 1) { issue(1); CP_COMMIT(); }
    else CP_COMMIT();

    for (int ci = 0; ci < nch; ci++) {
        if (ci + 2 < nch) issue(ci + 2);
        CP_COMMIT();                 // committed even when empty: keeps group count aligned
        CP_WAIT2();                  // chunk ci resident
        __syncthreads();

        const float* As = sm + (ci % STAGES) * STAGE_F;
        const float* Bs = As + TILE_F;

#pragma unroll
        for (int ks = 0; ks < 4; ks++) {
            uint32_t a[4][4], b[4][2];
            int kk = ks * 8 + (lane & 3);
#pragma unroll
            for (int mt = 0; mt < 4; mt++) {
                int r = wm * 64 + mt * 16 + (lane >> 2);
                a[mt][0] = __float_as_uint(As[r * ASTR + kk]);
                a[mt][1] = __float_as_uint(As[(r + 8) * ASTR + kk]);
                a[mt][2] = __float_as_uint(As[r * ASTR + kk + 4]);
                a[mt][3] = __float_as_uint(As[(r + 8) * ASTR + kk + 4]);
            }
#pragma unroll
            for (int nt = 0; nt < 4; nt++) {
                int n = wn * 32 + nt * 8 + (lane >> 2);
                b[nt][0] = __float_as_uint(Bs[n * ASTR + kk]);
                b[nt][1] = __float_as_uint(Bs[n * ASTR + kk + 4]);
            }
#pragma unroll
            for (int mt = 0; mt < 4; mt++)
#pragma unroll
                for (int nt = 0; nt < 4; nt++)
                    MMA8(acc[mt][nt], a[mt], b[nt]);
        }
        __syncthreads();
    }

    CP_WAIT0();
    __syncthreads();

    // Stage D through smem: Ds[col][row], stride 133 (reads conflict-free)
    float* Ds = sm;
#pragma unroll
    for (int mt = 0; mt < 4; mt++)
#pragma unroll
        for (int nt = 0; nt < 4; nt++) {
            int r = wm * 64 + mt * 16 + (lane >> 2);
            int c = wn * 32 + nt * 8 + (lane & 3) * 2;
            Ds[c * 133 + r]           = acc[mt][nt][0];
            Ds[(c + 1) * 133 + r]     = acc[mt][nt][1];
            Ds[c * 133 + r + 8]       = acc[mt][nt][2];
            Ds[(c + 1) * 133 + r + 8] = acc[mt][nt][3];
        }
    __syncthreads();

    if (MODE == 1) {
#pragma unroll 8
        for (int p = 0; p < 64; p++) {
            int e = p * 256 + tid; int r = e >> 7; int c = e & 127;
            g_s[(size_t)z * NSP * NSP + (size_t)(m0 + r) * NSP + n0 + c] = Ds[c * 133 + r];
        }
    } else if (MODE == 2) {
#pragma unroll 8
        for (int p = 0; p < 64; p++) {
            int e = p * 256 + tid; int r = e >> 7; int c = e & 127;
            g_ot[((size_t)(z >> 2) * NSP + m0 + r) * CH + (z & 3) * HD + c] = rnd_tf32(Ds[c * 133 + r]);
        }
    } else if (MODE == 0) {
        if (n0 < 1024) {   // Q/K -> g_qkvt[b][n][o]
#pragma unroll 8
            for (int p = 0; p < 64; p++) {
                int e = p * 256 + tid; int r = e >> 7; int c = e & 127;
                g_qkvt[((size_t)z * NSP + m0 + r) * 1536 + n0 + c] = rnd_tf32(Ds[c * 133 + r] + bias[n0 + c]);
            }
        } else {           // V transposed -> g_vt[b,h][d][m]
            int h = (n0 - 1024) >> 7;
#pragma unroll 8
            for (int p = 0; p < 64; p++) {
                int e = p * 256 + tid; int c = e >> 7; int r = e & 127;
                g_vt[(((size_t)z * HEADS + h) * HD + c) * NSP + m0 + r] = rnd_tf32(Ds[c * 133 + r] + bias[n0 + c]);
            }
        }
    } else {               // MODE 3: bias + residual, transposed -> out[b][o][n]
#pragma unroll 8
        for (int p = 0; p < 64; p++) {
            int e = p * 256 + tid; int c = e >> 7; int r = e & 127;
            size_t off = ((size_t)z * CH + n0 + c) * NSP + m0 + r;
            outp[off] = Ds[c * 133 + r] + bias[n0 + c] + resid[off];
        }
    }
}

// ---------------------------------------------------------------------------
// Launch
// ---------------------------------------------------------------------------
extern "C" void kernel_launch(void* const* d_in, const int* in_sizes, int n_in,
                              void* d_out, int out_size)
{
    const float* x      = (const float*)d_in[0];
    const float* norm_w = (const float*)d_in[1];
    const float* norm_b = (const float*)d_in[2];
    const float* qkv_w  = (const float*)d_in[3];
    const float* qkv_b  = (const float*)d_in[4];
    const float* proj_w = (const float*)d_in[5];
    const float* proj_b = (const float*)d_in[6];
    float* out = (float*)d_out;

    float* wq; cudaGetSymbolAddress((void**)&wq, g_wq);
    float* wp; cudaGetSymbolAddress((void**)&wp, g_wp);

    cudaFuncSetAttribute(gemm_tc<0>, cudaFuncAttributeMaxDynamicSharedMemorySize, GEMM_SMEM);
    cudaFuncSetAttribute(gemm_tc<1>, cudaFuncAttributeMaxDynamicSharedMemorySize, GEMM_SMEM);
    cudaFuncSetAttribute(gemm_tc<2>, cudaFuncAttributeMaxDynamicSharedMemorySize, GEMM_SMEM);
    cudaFuncSetAttribute(gemm_tc<3>, cudaFuncAttributeMaxDynamicSharedMemorySize, GEMM_SMEM);

    // 0. Weight tf32 pre-round
    cvtw_kernel<<<(3 * CH * CH + 255) / 256, 256>>>(qkv_w, proj_w);

    // 1. GroupNorm -> g_ht[b][n][c] (tf32)
    gn_kernel<<<BATCH * GROUPS_N, 256>>>(x, norm_w, norm_b);

    // 2. QKV: [n,o] = h[n][c] * Wqkv[o][c]^T  (per batch)
    gemm_tc<0><<<dim3(NSP / 128, 1536 / 128, BATCH), 256, GEMM_SMEM>>>(wq, nullptr, qkv_b, nullptr, nullptr);

    // 3. S = Q K^T  (per b,h)
    gemm_tc<1><<<dim3(NSP / 128, NSP / 128, BATCH * HEADS), 256, GEMM_SMEM>>>(nullptr, nullptr, nullptr, nullptr, nullptr);

    // 4. softmax in-place (tf32 probs)
    softmax_kernel<<<(BATCH * HEADS * NSP) / 8, 256>>>();

    // 5. O = P V^T  (per b,h)
    gemm_tc<2><<<dim3(NSP / 128, 1, BATCH * HEADS), 256, GEMM_SMEM>>>(nullptr, nullptr, nullptr, nullptr, nullptr);

    // 6. proj + bias + residual -> out
    gemm_tc<3><<<dim3(NSP / 128, CH / 128, BATCH), 256, GEMM_SMEM>>>(nullptr, wp, proj_b, x, out);
}

// round 4
// speedup vs baseline: 3.1145x; 1.0082x over previous
#include <cuda_runtime.h>
#include <cstdint>
#include <math.h>

#define BATCH 16
#define CH    512
#define NSP   1024
#define HEADS 4
#define HD    128
#define GROUPS_N 32
#define GSIZE (16*1024)
#define EPSV  1e-5f
#define ATT_SCALE 0.08838834764831845f

// ---------------------------------------------------------------------------
// Scratch (device globals). All GEMM operands stored pre-rounded to tf32.
// ---------------------------------------------------------------------------
__device__ float g_ht  [(size_t)BATCH*NSP*CH];
__device__ float g_qkvt[(size_t)BATCH*NSP*(3*CH)];
__device__ float g_vt  [(size_t)BATCH*HEADS*HD*NSP];
__device__ float g_s   [(size_t)BATCH*HEADS*NSP*NSP];
__device__ float g_ot  [(size_t)BATCH*NSP*CH];
__device__ float g_wq  [(size_t)(3*CH)*CH];
__device__ float g_wp  [(size_t)CH*CH];

// ---------------------------------------------------------------------------
// Helpers
// ---------------------------------------------------------------------------
__device__ __forceinline__ uint32_t smem_u32(const void* p){
    uint32_t a;
    asm("{ .reg .u64 t; cvta.to.shared.u64 t, %1; cvt.u32.u64 %0, t; }" : "=r"(a) : "l"(p));
    return a;
}
__device__ __forceinline__ uint32_t cvt_tf32(float f){
    uint32_t o; asm("cvt.rna.tf32.f32 %0, %1;" : "=r"(o) : "f"(f)); return o;
}
__device__ __forceinline__ float rnd_tf32(float f){ return __uint_as_float(cvt_tf32(f)); }

__device__ __forceinline__ void cp16(uint32_t dst, const float* src){
    asm volatile("cp.async.cg.shared.global [%0], [%1], 16;" :: "r"(dst), "l"(src) : "memory");
}
#define CP_COMMIT() asm volatile("cp.async.commit_group;" ::: "memory")
#define CP_WAIT2()  asm volatile("cp.async.wait_group 2;" ::: "memory")
#define CP_WAIT0()  asm volatile("cp.async.wait_group 0;" ::: "memory")

#define MMA8(c, a, b) \
    asm volatile("mma.sync.aligned.m16n8k8.row.col.f32.tf32.tf32.f32 " \
        "{%0,%1,%2,%3},{%4,%5,%6,%7},{%8,%9},{%0,%1,%2,%3};" \
        : "+f"((c)[0]), "+f"((c)[1]), "+f"((c)[2]), "+f"((c)[3]) \
        : "r"((a)[0]), "r"((a)[1]), "r"((a)[2]), "r"((a)[3]), \
          "r"((b)[0]), "r"((b)[1]))

// ---------------------------------------------------------------------------
// Weight pre-round
// ---------------------------------------------------------------------------
__global__ __launch_bounds__(256) void cvtw_kernel(
    const float* __restrict__ qw, const float* __restrict__ pw)
{
    int i = blockIdx.x * 256 + threadIdx.x;
    if (i < 3*CH*CH) g_wq[i] = rnd_tf32(qw[i]);
    if (i < CH*CH)   g_wp[i] = rnd_tf32(pw[i]);
}

// ---------------------------------------------------------------------------
// GroupNorm + transpose -> g_ht[b][n][c], tf32-rounded
// ---------------------------------------------------------------------------
__global__ __launch_bounds__(256) void gn_kernel(
    const float* __restrict__ x,
    const float* __restrict__ nw,
    const float* __restrict__ nb)
{
    __shared__ float t[16][257];
    int bg = blockIdx.x;
    int b = bg >> 5, g = bg & 31;
    const float* xp = x + (size_t)bg * GSIZE;
    int tid = threadIdx.x;

    float s = 0.f, s2 = 0.f;
    for (int i = tid; i < GSIZE; i += 256) { float v = xp[i]; s += v; s2 += v * v; }
    float* rs  = &t[0][0];
    float* rs2 = rs + 1024;
    rs[tid] = s; rs2[tid] = s2;
    __syncthreads();
    for (int o = 128; o > 0; o >>= 1) {
        if (tid < o) { rs[tid] += rs[tid + o]; rs2[tid] += rs2[tid + o]; }
        __syncthreads();
    }
    float mu   = rs[0] * (1.f / GSIZE);
    float var  = rs2[0] * (1.f / GSIZE) - mu * mu;
    float rinv = rsqrtf(var + EPSV);
    __syncthreads();

    int cl = tid & 15;
    float wc = nw[g * 16 + cl] * rinv;
    float bc = nb[g * 16 + cl] - mu * wc;
    float* hp = g_ht + (size_t)b * NSP * CH + g * 16;

    for (int n0 = 0; n0 < NSP; n0 += 256) {
#pragma unroll
        for (int c = 0; c < 16; c++) t[c][tid] = xp[c * NSP + n0 + tid];
        __syncthreads();
#pragma unroll
        for (int j = 0; j < 16; j++) {
            int nn = (tid >> 4) + j * 16;
            hp[(size_t)(n0 + nn) * CH + cl] = rnd_tf32(t[cl][nn] * wc + bc);
        }
        __syncthreads();
    }
}

// ---------------------------------------------------------------------------
// Softmax in-place over g_s rows; output probs tf32-rounded.
// ---------------------------------------------------------------------------
__global__ __launch_bounds__(256) void softmax_kernel()
{
    size_t row = (size_t)blockIdx.x * 8 + (threadIdx.x >> 5);
    int l = threadIdx.x & 31;
    float4* sp = (float4*)(g_s + row * NSP);

    float4 v[8];
    float m = -1e30f;
#pragma unroll
    for (int t = 0; t < 8; t++) {
        v[t] = sp[t * 32 + l];
        v[t].x *= ATT_SCALE; v[t].y *= ATT_SCALE; v[t].z *= ATT_SCALE; v[t].w *= ATT_SCALE;
        m = fmaxf(m, fmaxf(fmaxf(v[t].x, v[t].y), fmaxf(v[t].z, v[t].w)));
    }
#pragma unroll
    for (int o = 16; o > 0; o >>= 1) m = fmaxf(m, __shfl_xor_sync(0xffffffffu, m, o));
    float s = 0.f;
#pragma unroll
    for (int t = 0; t < 8; t++) {
        v[t].x = __expf(v[t].x - m); v[t].y = __expf(v[t].y - m);
        v[t].z = __expf(v[t].z - m); v[t].w = __expf(v[t].w - m);
        s += v[t].x + v[t].y + v[t].z + v[t].w;
    }
#pragma unroll
    for (int o = 16; o > 0; o >>= 1) s += __shfl_xor_sync(0xffffffffu, s, o);
    float inv = 1.f / s;
#pragma unroll
    for (int t = 0; t < 8; t++) {
        v[t].x = rnd_tf32(v[t].x * inv); v[t].y = rnd_tf32(v[t].y * inv);
        v[t].z = rnd_tf32(v[t].z * inv); v[t].w = rnd_tf32(v[t].w * inv);
        sp[t * 32 + l] = v[t];
    }
}

// ---------------------------------------------------------------------------
// tf32 mma.sync GEMM: D[128m x 128n] = A[m][K] * B[n][K]^T (both K-major)
// 128 threads = 4 warps (2 x 2); warp tile 64x64; explicit register
// double-buffering of fragments; 3-stage cp.async pipeline; K-chunk 32.
// ---------------------------------------------------------------------------
#define BK 32
#define ASTR 36
#define TILE_F (128*ASTR)
#define STAGE_F (2*TILE_F)
#define STAGES 3
#define GEMM_SMEM (STAGES*STAGE_F*4)   // 110592 bytes

template<int MODE>
__global__ __launch_bounds__(128) void gemm_tc(
    const float* __restrict__ Wq, const float* __restrict__ Wp,
    const float* __restrict__ bias,
    const float* __restrict__ resid, float* __restrict__ outp)
{
    extern __shared__ float sm[];
    const int tid = threadIdx.x;
    uint32_t smb = smem_u32(sm);

    int m0 = blockIdx.x * 128;
    int n0 = blockIdx.y * 128;
    int z  = blockIdx.z;

    const float *A, *B;
    int lda, ldb, K;
    if (MODE == 0) {
        A = g_ht + ((size_t)z * NSP + m0) * CH; lda = CH;
        B = Wq + (size_t)n0 * CH;               ldb = CH;  K = CH;
    } else if (MODE == 1) {
        int b = z >> 2, h = z & 3;
        const float* base = g_qkvt + (size_t)b * NSP * 1536;
        A = base + (size_t)m0 * 1536 + h * HD;
        B = base + (size_t)n0 * 1536 + 512 + h * HD;
        lda = 1536; ldb = 1536; K = HD;
    } else if (MODE == 2) {
        A = g_s  + (size_t)z * NSP * NSP + (size_t)m0 * NSP; lda = NSP; K = NSP;
        B = g_vt + (size_t)z * HD * NSP;                     ldb = NSP;
    } else {
        A = g_ot + ((size_t)z * NSP + m0) * CH; lda = CH;
        B = Wp + (size_t)n0 * CH;               ldb = CH;  K = CH;
    }

    const int lane = tid & 31, wid = tid >> 5;
    const int wm = wid & 1, wn = wid >> 1;     // 2 x 2 warp grid, 64x64 tiles
    const int r_ = tid >> 3;                   // 0..15
    const int f_ = tid & 7;                    // 0..7

    float acc[4][8][4];
#pragma unroll
    for (int i = 0; i < 4; i++)
#pragma unroll
        for (int j = 0; j < 8; j++)
#pragma unroll
            for (int q = 0; q < 4; q++) acc[i][j][q] = 0.f;

    const int nch = K / BK;

    auto issue = [&](int ci) {
        int s = ci % STAGES;
        uint32_t as = smb + (uint32_t)(s * STAGE_F) * 4u;
        uint32_t bs = as + (uint32_t)TILE_F * 4u;
        int k0 = ci * BK;
#pragma unroll
        for (int t = 0; t < 8; t++) {
            int r = t * 16 + r_;
            cp16(as + (uint32_t)(r * ASTR + f_ * 4) * 4u, A + (size_t)r * lda + k0 + f_ * 4);
            cp16(bs + (uint32_t)(r * ASTR + f_ * 4) * 4u, B + (size_t)r * ldb + k0 + f_ * 4);
        }
    };

    issue(0); CP_COMMIT();
    if (nch > 1) { issue(1); CP_COMMIT(); }
    else CP_COMMIT();

    const int rA = lane >> 2, kA = lane & 3;

    for (int ci = 0; ci < nch; ci++) {
        if (ci + 2 < nch) issue(ci + 2);
        CP_COMMIT();
        CP_WAIT2();
        __syncthreads();

        const float* As = sm + (ci % STAGES) * STAGE_F;
        const float* Bs = As + TILE_F;

        // fragment double-buffer across the 4 k8-steps
        uint32_t a[2][4][4], b[2][8][2];

        {
            int kk = kA;            // ks = 0
#pragma unroll
            for (int mt = 0; mt < 4; mt++) {
                int r = wm * 64 + mt * 16 + rA;
                a[0][mt][0] = __float_as_uint(As[r * ASTR + kk]);
                a[0][mt][1] = __float_as_uint(As[(r + 8) * ASTR + kk]);
                a[0][mt][2] = __float_as_uint(As[r * ASTR + kk + 4]);
                a[0][mt][3] = __float_as_uint(As[(r + 8) * ASTR + kk + 4]);
            }
#pragma unroll
            for (int nt = 0; nt < 8; nt++) {
                int n = wn * 64 + nt * 8 + rA;
                b[0][nt][0] = __float_as_uint(Bs[n * ASTR + kk]);
                b[0][nt][1] = __float_as_uint(Bs[n * ASTR + kk + 4]);
            }
        }

#pragma unroll
        for (int ks = 0; ks < 4; ks++) {
            int cur = ks & 1, nxt = cur ^ 1;
            if (ks < 3) {
                int kk = (ks + 1) * 8 + kA;
#pragma unroll
                for (int mt = 0; mt < 4; mt++) {
                    int r = wm * 64 + mt * 16 + rA;
                    a[nxt][mt][0] = __float_as_uint(As[r * ASTR + kk]);
                    a[nxt][mt][1] = __float_as_uint(As[(r + 8) * ASTR + kk]);
                    a[nxt][mt][2] = __float_as_uint(As[r * ASTR + kk + 4]);
                    a[nxt][mt][3] = __float_as_uint(As[(r + 8) * ASTR + kk + 4]);
                }
#pragma unroll
                for (int nt = 0; nt < 8; nt++) {
                    int n = wn * 64 + nt * 8 + rA;
                    b[nxt][nt][0] = __float_as_uint(Bs[n * ASTR + kk]);
                    b[nxt][nt][1] = __float_as_uint(Bs[n * ASTR + kk + 4]);
                }
            }
#pragma unroll
            for (int mt = 0; mt < 4; mt++)
#pragma unroll
                for (int nt = 0; nt < 8; nt++)
                    MMA8(acc[mt][nt], a[cur][mt], b[cur][nt]);
        }
        __syncthreads();
    }

    CP_WAIT0();
    __syncthreads();

    // Stage D through smem: Ds[col][row], stride 133
    float* Ds = sm;
#pragma unroll
    for (int mt = 0; mt < 4; mt++)
#pragma unroll
        for (int nt = 0; nt < 8; nt++) {
            int r = wm * 64 + mt * 16 + (lane >> 2);
            int c = wn * 64 + nt * 8 + (lane & 3) * 2;
            Ds[c * 133 + r]           = acc[mt][nt][0];
            Ds[(c + 1) * 133 + r]     = acc[mt][nt][1];
            Ds[c * 133 + r + 8]       = acc[mt][nt][2];
            Ds[(c + 1) * 133 + r + 8] = acc[mt][nt][3];
        }
    __syncthreads();

    if (MODE == 1) {
#pragma unroll 8
        for (int p = 0; p < 128; p++) {
            int e = p * 128 + tid; int r = e >> 7; int c = e & 127;
            g_s[(size_t)z * NSP * NSP + (size_t)(m0 + r) * NSP + n0 + c] = Ds[c * 133 + r];
        }
    } else if (MODE == 2) {
#pragma unroll 8
        for (int p = 0; p < 128; p++) {
            int e = p * 128 + tid; int r = e >> 7; int c = e & 127;
            g_ot[((size_t)(z >> 2) * NSP + m0 + r) * CH + (z & 3) * HD + c] = rnd_tf32(Ds[c * 133 + r]);
        }
    } else if (MODE == 0) {
        if (n0 < 1024) {
#pragma unroll 8
            for (int p = 0; p < 128; p++) {
                int e = p * 128 + tid; int r = e >> 7; int c = e & 127;
                g_qkvt[((size_t)z * NSP + m0 + r) * 1536 + n0 + c] = rnd_tf32(Ds[c * 133 + r] + bias[n0 + c]);
            }
        } else {
            int h = (n0 - 1024) >> 7;
#pragma unroll 8
            for (int p = 0; p < 128; p++) {
                int e = p * 128 + tid; int c = e >> 7; int r = e & 127;
                g_vt[(((size_t)z * HEADS + h) * HD + c) * NSP + m0 + r] = rnd_tf32(Ds[c * 133 + r] + bias[n0 + c]);
            }
        }
    } else {
#pragma unroll 8
        for (int p = 0; p < 128; p++) {
            int e = p * 128 + tid; int c = e >> 7; int r = e & 127;
            size_t off = ((size_t)z * CH + n0 + c) * NSP + m0 + r;
            outp[off] = Ds[c * 133 + r] + bias[n0 + c] + resid[off];
        }
    }
}

// ---------------------------------------------------------------------------
// Launch
// ---------------------------------------------------------------------------
extern "C" void kernel_launch(void* const* d_in, const int* in_sizes, int n_in,
                              void* d_out, int out_size)
{
    const float* x      = (const float*)d_in[0];
    const float* norm_w = (const float*)d_in[1];
    const float* norm_b = (const float*)d_in[2];
    const float* qkv_w  = (const float*)d_in[3];
    const float* qkv_b  = (const float*)d_in[4];
    const float* proj_w = (const float*)d_in[5];
    const float* proj_b = (const float*)d_in[6];
    float* out = (float*)d_out;

    float* wq; cudaGetSymbolAddress((void**)&wq, g_wq);
    float* wp; cudaGetSymbolAddress((void**)&wp, g_wp);

    cudaFuncSetAttribute(gemm_tc<0>, cudaFuncAttributeMaxDynamicSharedMemorySize, GEMM_SMEM);
    cudaFuncSetAttribute(gemm_tc<1>, cudaFuncAttributeMaxDynamicSharedMemorySize, GEMM_SMEM);
    cudaFuncSetAttribute(gemm_tc<2>, cudaFuncAttributeMaxDynamicSharedMemorySize, GEMM_SMEM);
    cudaFuncSetAttribute(gemm_tc<3>, cudaFuncAttributeMaxDynamicSharedMemorySize, GEMM_SMEM);

    cvtw_kernel<<<(3 * CH * CH + 255) / 256, 256>>>(qkv_w, proj_w);
    gn_kernel<<<BATCH * GROUPS_N, 256>>>(x, norm_w, norm_b);

    gemm_tc<0><<<dim3(NSP / 128, 1536 / 128, BATCH), 128, GEMM_SMEM>>>(wq, nullptr, qkv_b, nullptr, nullptr);
    gemm_tc<1><<<dim3(NSP / 128, NSP / 128, BATCH * HEADS), 128, GEMM_SMEM>>>(nullptr, nullptr, nullptr, nullptr, nullptr);
    softmax_kernel<<<(BATCH * HEADS * NSP) / 8, 256>>>();
    gemm_tc<2><<<dim3(NSP / 128, 1, BATCH * HEADS), 128, GEMM_SMEM>>>(nullptr, nullptr, nullptr, nullptr, nullptr);
    gemm_tc<3><<<dim3(NSP / 128, CH / 128, BATCH), 128, GEMM_SMEM>>>(nullptr, wp, proj_b, x, out);
}